// round 1
// baseline (speedup 1.0000x reference)
#include <cuda_runtime.h>
#include <cuda_fp16.h>
#include <cstdint>
#include <cstddef>

#define L_SEQ 512
#define BATCH 128
#define DIM   128
#define HID   512
#define OUTD  5
#define N3H   1536
#define MROWS 65536  // L_SEQ*BATCH

// ---------------- scratch (static device globals; no allocations) ----------------
__device__ __align__(256) __half g_xh[MROWS * DIM];          // x in fp16
__device__ __align__(256) __half g_W0t[N3H * DIM];           // W0^T fp16 [n][k]
__device__ __align__(256) __half g_W1t[N3H * HID];           // W1^T fp16 [n][k]
__device__ __align__(256) __half g_U[MROWS * N3H];           // U buffer (reused for both layers)
__device__ __align__(256) __half g_h1[MROWS * HID];          // layer-0 output
__device__ __align__(256) float  g_h2last[BATCH * HID];      // layer-1 last-step output

// ---------------- conversion kernels ----------------
__global__ void f2h_kernel(const float* __restrict__ s, __half* __restrict__ d, int n2)
{
    int i = blockIdx.x * blockDim.x + threadIdx.x;
    if (i < n2) {
        float2 v = reinterpret_cast<const float2*>(s)[i];
        reinterpret_cast<__half2*>(d)[i] = __floats2half2_rn(v.x, v.y);
    }
}

// Wt[n][k] = (half) W[k][n]
__global__ void f2h_t_kernel(const float* __restrict__ W, __half* __restrict__ Wt, int K, int N)
{
    int i = blockIdx.x * blockDim.x + threadIdx.x;
    if (i < K * N) {
        int k = i / N;
        int n = i - k * N;
        Wt[n * K + k] = __float2half(W[i]);
    }
}

// ---------------- GEMM: C[m][n] (fp16, ld=N3H) = A[m][k] * B^T where B given as [n][k] ----------------
__device__ __forceinline__ uint32_t smem_cast(const void* p)
{
    return (uint32_t)__cvta_generic_to_shared(p);
}

#define CP_ASYNC16(dst, src) asm volatile("cp.async.cg.shared.global [%0], [%1], 16;\n" :: "r"(dst), "l"(src))
#define CP_COMMIT()          asm volatile("cp.async.commit_group;\n")
#define CP_WAIT0()           asm volatile("cp.async.wait_group 0;\n")
#define CP_WAIT1()           asm volatile("cp.async.wait_group 1;\n")

#define LDSM4(R0, R1, R2, R3, ADDR) \
    asm volatile("ldmatrix.sync.aligned.m8n8.x4.shared.b16 {%0,%1,%2,%3}, [%4];" \
                 : "=r"(R0), "=r"(R1), "=r"(R2), "=r"(R3) : "r"(ADDR))

#define MMA16816(C0, C1, C2, C3, A0, A1, A2, A3, B0, B1)                              \
    asm volatile("mma.sync.aligned.m16n8k16.row.col.f32.f16.f16.f32 "                  \
                 "{%0,%1,%2,%3}, {%4,%5,%6,%7}, {%8,%9}, {%0,%1,%2,%3};"               \
                 : "+f"(C0), "+f"(C1), "+f"(C2), "+f"(C3)                              \
                 : "r"(A0), "r"(A1), "r"(A2), "r"(A3), "r"(B0), "r"(B1))

// 16B-granule XOR swizzle. Logical tile: 128 rows x 32 halfs. Two logical rows share
// one 128B physical row (8 granules) so ldmatrix row-walks are bank-conflict-free.
__device__ __forceinline__ int sw_gran(int row, int seg)
{
    return ((row >> 1) << 3) | ((((row & 1) << 2) | seg) ^ ((row >> 1) & 7));
}

__global__ void __launch_bounds__(256, 2) gemm_kernel(
    const __half* __restrict__ A,   // [M][K]
    const __half* __restrict__ B,   // [N][K] (pre-transposed weights)
    __half* __restrict__ C,         // [M][N3H]
    int K)
{
    __shared__ __align__(1024) __half As[2][128 * 32];
    __shared__ __align__(1024) __half Bs[2][128 * 32];

    const int tid  = threadIdx.x;
    const int lane = tid & 31;
    const int wid  = tid >> 5;
    const int wm   = wid & 3;    // 4 warps along M (32 rows each)
    const int wn   = wid >> 2;   // 2 warps along N (64 cols each)
    const int m0   = blockIdx.y * 128;
    const int n0   = blockIdx.x * 128;

    auto load_tile = [&](int buf, int k0) {
        uint32_t as = smem_cast(&As[buf][0]);
        uint32_t bs = smem_cast(&Bs[buf][0]);
#pragma unroll
        for (int i = 0; i < 2; i++) {
            int lin = tid + i * 256;       // 0..511
            int row = lin >> 2;            // 0..127
            int seg = lin & 3;             // 16B segment within 32-half row
            int g   = sw_gran(row, seg);
            const __half* ag = A + (size_t)(m0 + row) * K + (k0 + seg * 8);
            const __half* bg = B + (size_t)(n0 + row) * K + (k0 + seg * 8);
            CP_ASYNC16(as + g * 16, ag);
            CP_ASYNC16(bs + g * 16, bg);
        }
    };

    float acc[2][8][4];
#pragma unroll
    for (int mi = 0; mi < 2; mi++)
#pragma unroll
        for (int ni = 0; ni < 8; ni++)
#pragma unroll
            for (int j = 0; j < 4; j++) acc[mi][ni][j] = 0.f;

    const int T = K >> 5;
    load_tile(0, 0);
    CP_COMMIT();

    // ldmatrix lane geometry
    const int a_row_base = wm * 32 + (lane & 15);
    const int a_koff     = lane >> 4;                               // 0/1
    const int b_row_base = wn * 64 + (lane & 7) + ((lane & 16) ? 8 : 0);
    const int b_koff     = (lane >> 3) & 1;

    for (int t = 0; t < T; t++) {
        int cur = t & 1;
        if (t + 1 < T) {
            load_tile(cur ^ 1, (t + 1) << 5);
            CP_COMMIT();
            CP_WAIT1();
        } else {
            CP_WAIT0();
        }
        __syncthreads();

        uint32_t as = smem_cast(&As[cur][0]);
        uint32_t bs = smem_cast(&Bs[cur][0]);
#pragma unroll
        for (int kc = 0; kc < 2; kc++) {
            uint32_t a[2][4];
#pragma unroll
            for (int mi = 0; mi < 2; mi++) {
                int row = a_row_base + mi * 16;
                int seg = kc * 2 + a_koff;
                uint32_t addr = as + sw_gran(row, seg) * 16;
                LDSM4(a[mi][0], a[mi][1], a[mi][2], a[mi][3], addr);
            }
            uint32_t bf[8][2];
#pragma unroll
            for (int nb = 0; nb < 4; nb++) {
                int row = b_row_base + nb * 16;
                int seg = kc * 2 + b_koff;
                uint32_t addr = bs + sw_gran(row, seg) * 16;
                LDSM4(bf[2 * nb][0], bf[2 * nb][1], bf[2 * nb + 1][0], bf[2 * nb + 1][1], addr);
            }
#pragma unroll
            for (int mi = 0; mi < 2; mi++)
#pragma unroll
                for (int ni = 0; ni < 8; ni++)
                    MMA16816(acc[mi][ni][0], acc[mi][ni][1], acc[mi][ni][2], acc[mi][ni][3],
                             a[mi][0], a[mi][1], a[mi][2], a[mi][3],
                             bf[ni][0], bf[ni][1]);
        }
        __syncthreads();
    }

    // epilogue: fp32 accum -> fp16 C
#pragma unroll
    for (int mi = 0; mi < 2; mi++) {
        int m = m0 + wm * 32 + mi * 16 + (lane >> 2);
#pragma unroll
        for (int ni = 0; ni < 8; ni++) {
            int n = n0 + wn * 64 + ni * 8 + (lane & 3) * 2;
            __half2 lo = __floats2half2_rn(acc[mi][ni][0], acc[mi][ni][1]);
            __half2 hi = __floats2half2_rn(acc[mi][ni][2], acc[mi][ni][3]);
            *reinterpret_cast<__half2*>(C + (size_t)m * N3H + n)       = lo;
            *reinterpret_cast<__half2*>(C + (size_t)(m + 8) * N3H + n) = hi;
        }
    }
}

// ---------------- SRU recurrence ----------------
__device__ __forceinline__ float sigf(float x)
{
    // accurate fast sigmoid: 2 MUFU (EX2 + RCP), rel err ~1e-6
    return __fdividef(1.f, 1.f + __expf(-x));
}

__global__ void __launch_bounds__(256) sru_rec_kernel(
    const __half* __restrict__ U,    // [L*B][3H] fp16
    const float* __restrict__ v,     // [2H]
    const float* __restrict__ bb,    // [2H]
    __half* __restrict__ hout,       // [L*B][H] fp16 (if store_all)
    float* __restrict__ hlast,       // [B][H] fp32 (if !store_all)
    int store_all)
{
    int idx = blockIdx.x * blockDim.x + threadIdx.x;  // 0..32767
    int b  = idx >> 8;        // batch
    int hp = idx & 255;       // half2 channel index
    int h  = hp << 1;

    float2 vf = *reinterpret_cast<const float2*>(v + h);
    float2 vr = *reinterpret_cast<const float2*>(v + HID + h);
    float2 bf = *reinterpret_cast<const float2*>(bb + h);
    float2 br = *reinterpret_cast<const float2*>(bb + HID + h);

    const __half2* Up = reinterpret_cast<const __half2*>(U) + b * (N3H / 2) + hp;
    __half2* Hp       = reinterpret_cast<__half2*>(hout) + b * (HID / 2) + hp;

    float cx = 0.f, cy = 0.f;
    float hx = 0.f, hy = 0.f;

    for (int l = 0; l < L_SEQ; l++) {
        float2 u0 = __half22float2(Up[0]);
        float2 u1 = __half22float2(Up[HID / 2]);   // +256 half2
        float2 u2 = __half22float2(Up[HID]);       // +512 half2

        float fxa = sigf(fmaf(vf.x, cx, u1.x + bf.x));
        float fya = sigf(fmaf(vf.y, cy, u1.y + bf.y));
        float rxa = sigf(fmaf(vr.x, cx, u2.x + br.x));
        float rya = sigf(fmaf(vr.y, cy, u2.y + br.y));

        cx = fmaf(fxa, cx - u0.x, u0.x);
        cy = fmaf(fya, cy - u0.y, u0.y);
        hx = rxa * cx;
        hy = rya * cy;

        if (store_all) *Hp = __floats2half2_rn(hx, hy);

        Up += BATCH * (N3H / 2);
        Hp += BATCH * (HID / 2);
    }

    if (!store_all) {
        hlast[b * HID + h]     = hx;
        hlast[b * HID + h + 1] = hy;
    }
}

// ---------------- final FC: out[b][o] = h2last[b] . fc_w[o] + fc_b[o] ----------------
__global__ void fc_kernel(const float* __restrict__ hl, const float* __restrict__ w,
                          const float* __restrict__ bias, float* __restrict__ out)
{
    int o = blockIdx.x;  // 0..4
    int b = blockIdx.y;  // 0..127
    float p = 0.f;
    for (int h = threadIdx.x; h < HID; h += 128)
        p += hl[b * HID + h] * w[o * HID + h];
#pragma unroll
    for (int s = 16; s > 0; s >>= 1) p += __shfl_down_sync(0xffffffffu, p, s);
    __shared__ float red[4];
    if ((threadIdx.x & 31) == 0) red[threadIdx.x >> 5] = p;
    __syncthreads();
    if (threadIdx.x == 0)
        out[b * OUTD + o] = red[0] + red[1] + red[2] + red[3] + bias[o];
}

// ---------------- launch ----------------
extern "C" void kernel_launch(void* const* d_in, const int* in_sizes, int n_in,
                              void* d_out, int out_size)
{
    const float* x   = (const float*)d_in[0];
    const float* W0  = (const float*)d_in[1];
    const float* v0  = (const float*)d_in[2];
    const float* b0  = (const float*)d_in[3];
    const float* W1  = (const float*)d_in[4];
    const float* v1  = (const float*)d_in[5];
    const float* b1  = (const float*)d_in[6];
    const float* fcw = (const float*)d_in[7];
    const float* fcb = (const float*)d_in[8];
    float* out = (float*)d_out;

    void *p_xh, *p_w0t, *p_w1t, *p_u, *p_h1, *p_h2l;
    cudaGetSymbolAddress(&p_xh,  g_xh);
    cudaGetSymbolAddress(&p_w0t, g_W0t);
    cudaGetSymbolAddress(&p_w1t, g_W1t);
    cudaGetSymbolAddress(&p_u,   g_U);
    cudaGetSymbolAddress(&p_h1,  g_h1);
    cudaGetSymbolAddress(&p_h2l, g_h2last);
    __half* xh  = (__half*)p_xh;
    __half* w0t = (__half*)p_w0t;
    __half* w1t = (__half*)p_w1t;
    __half* U   = (__half*)p_u;
    __half* h1  = (__half*)p_h1;
    float*  h2l = (float*)p_h2l;

    const int nx2 = MROWS * DIM / 2;
    f2h_kernel<<<(nx2 + 255) / 256, 256>>>(x, xh, nx2);
    f2h_t_kernel<<<(DIM * N3H + 255) / 256, 256>>>(W0, w0t, DIM, N3H);
    f2h_t_kernel<<<(HID * N3H + 255) / 256, 256>>>(W1, w1t, HID, N3H);

    // layer 0
    gemm_kernel<<<dim3(N3H / 128, MROWS / 128), 256>>>(xh, w0t, U, DIM);
    sru_rec_kernel<<<BATCH * HID / 2 / 256, 256>>>(U, v0, b0, h1, h2l, 1);

    // layer 1
    gemm_kernel<<<dim3(N3H / 128, MROWS / 128), 256>>>(h1, w1t, U, HID);
    sru_rec_kernel<<<BATCH * HID / 2 / 256, 256>>>(U, v1, b1, h1, h2l, 0);

    // head
    fc_kernel<<<dim3(OUTD, BATCH), 128>>>(h2l, fcw, fcb, out);
}

// round 2
// speedup vs baseline: 1.3295x; 1.3295x over previous
#include <cuda_runtime.h>
#include <cuda_fp16.h>
#include <cstdint>
#include <cstddef>

#define L_SEQ 512
#define BATCH 128
#define DIM   128
#define HID   512
#define OUTD  5
#define N3H   1536
#define MROWS 65536  // L_SEQ*BATCH

// ---------------- scratch (static device globals; no allocations) ----------------
__device__ __align__(256) __half g_xh[MROWS * DIM];          // x in fp16
__device__ __align__(256) __half g_W0t[N3H * DIM];           // W0^T fp16 [n][k]
__device__ __align__(256) __half g_W1t[N3H * HID];           // W1^T fp16 [n][k]
__device__ __align__(256) __half g_U[MROWS * N3H];           // U buffer (reused for both layers)
__device__ __align__(256) __half g_h1[MROWS * HID];          // layer-0 output
__device__ __align__(256) float  g_h2last[BATCH * HID];      // layer-1 last-step output

// ---------------- helpers ----------------
__device__ __forceinline__ uint32_t smem_cast(const void* p)
{
    return (uint32_t)__cvta_generic_to_shared(p);
}

#define CP_ASYNC16(dst, src) asm volatile("cp.async.cg.shared.global [%0], [%1], 16;\n" :: "r"(dst), "l"(src))
#define CP_COMMIT()          asm volatile("cp.async.commit_group;\n")
#define CP_WAIT1()           asm volatile("cp.async.wait_group 1;\n")
#define CP_WAIT6()           asm volatile("cp.async.wait_group 6;\n")

// ---------------- conversion kernels ----------------
__global__ void f2h_kernel(const float* __restrict__ s, __half* __restrict__ d, int n2)
{
    int i = blockIdx.x * blockDim.x + threadIdx.x;
    if (i < n2) {
        float2 v = reinterpret_cast<const float2*>(s)[i];
        reinterpret_cast<__half2*>(d)[i] = __floats2half2_rn(v.x, v.y);
    }
}

// Tiled transpose + fp32->fp16: Wt[n][k] = (half) W[k][n].  K rows, N cols, both %32==0.
__global__ void trans_f2h_kernel(const float* __restrict__ W, __half* __restrict__ Wt,
                                 int K, int N)
{
    __shared__ float tile[32][33];
    int tx = threadIdx.x;           // 0..31
    int ty = threadIdx.y;           // 0..7
    int nb = blockIdx.x * 32;       // col block in W (= n)
    int kb = blockIdx.y * 32;       // row block in W (= k)
#pragma unroll
    for (int j = 0; j < 32; j += 8)
        tile[ty + j][tx] = W[(size_t)(kb + ty + j) * N + (nb + tx)];
    __syncthreads();
#pragma unroll
    for (int j = 0; j < 32; j += 8)
        Wt[(size_t)(nb + ty + j) * K + (kb + tx)] = __float2half(tile[tx][ty + j]);
}

// ---------------- GEMM: C[m][n] (fp16, ld=N3H) = A[m][k] * B^T where B given as [n][k] ----------------
#define LDSM4(R0, R1, R2, R3, ADDR) \
    asm volatile("ldmatrix.sync.aligned.m8n8.x4.shared.b16 {%0,%1,%2,%3}, [%4];" \
                 : "=r"(R0), "=r"(R1), "=r"(R2), "=r"(R3) : "r"(ADDR))

#define MMA16816(C0, C1, C2, C3, A0, A1, A2, A3, B0, B1)                              \
    asm volatile("mma.sync.aligned.m16n8k16.row.col.f32.f16.f16.f32 "                  \
                 "{%0,%1,%2,%3}, {%4,%5,%6,%7}, {%8,%9}, {%0,%1,%2,%3};"               \
                 : "+f"(C0), "+f"(C1), "+f"(C2), "+f"(C3)                              \
                 : "r"(A0), "r"(A1), "r"(A2), "r"(A3), "r"(B0), "r"(B1))

// 16B-granule XOR swizzle. Logical tile: 128 rows x 32 halfs. Two logical rows share
// one 128B physical row (8 granules) so ldmatrix row-walks are bank-conflict-free.
__device__ __forceinline__ int sw_gran(int row, int seg)
{
    return ((row >> 1) << 3) | ((((row & 1) << 2) | seg) ^ ((row >> 1) & 7));
}

__global__ void __launch_bounds__(256, 2) gemm_kernel(
    const __half* __restrict__ A,   // [M][K]
    const __half* __restrict__ B,   // [N][K] (pre-transposed weights)
    __half* __restrict__ C,         // [M][N3H]
    int K)
{
    __shared__ __align__(1024) __half As[3][128 * 32];
    __shared__ __align__(1024) __half Bs[3][128 * 32];

    const int tid  = threadIdx.x;
    const int lane = tid & 31;
    const int wid  = tid >> 5;
    const int wm   = wid & 3;    // 4 warps along M (32 rows each)
    const int wn   = wid >> 2;   // 2 warps along N (64 cols each)
    const int m0   = blockIdx.y * 128;
    const int n0   = blockIdx.x * 128;

    auto load_tile = [&](int buf, int k0) {
        uint32_t as = smem_cast(&As[buf][0]);
        uint32_t bs = smem_cast(&Bs[buf][0]);
#pragma unroll
        for (int i = 0; i < 2; i++) {
            int lin = tid + i * 256;       // 0..511
            int row = lin >> 2;            // 0..127
            int seg = lin & 3;             // 16B segment within 32-half row
            int g   = sw_gran(row, seg);
            const __half* ag = A + (size_t)(m0 + row) * K + (k0 + seg * 8);
            const __half* bg = B + (size_t)(n0 + row) * K + (k0 + seg * 8);
            CP_ASYNC16(as + g * 16, ag);
            CP_ASYNC16(bs + g * 16, bg);
        }
    };

    float acc[2][8][4];
#pragma unroll
    for (int mi = 0; mi < 2; mi++)
#pragma unroll
        for (int ni = 0; ni < 8; ni++)
#pragma unroll
            for (int j = 0; j < 4; j++) acc[mi][ni][j] = 0.f;

    const int T = K >> 5;
    load_tile(0, 0);
    CP_COMMIT();
    load_tile(1, 32);
    CP_COMMIT();

    // ldmatrix lane geometry
    const int a_row_base = wm * 32 + (lane & 15);
    const int a_koff     = lane >> 4;                               // 0/1
    const int b_row_base = wn * 64 + (lane & 7) + ((lane & 16) ? 8 : 0);
    const int b_koff     = (lane >> 3) & 1;

    for (int t = 0; t < T; t++) {
        CP_WAIT1();            // tile t resident
        __syncthreads();       // visible to all threads; stage (t-1)%3 fully consumed

        if (t + 2 < T) load_tile((t + 2) % 3, (t + 2) << 5);
        CP_COMMIT();           // unconditional: keeps group count uniform

        int cur = t % 3;
        uint32_t as = smem_cast(&As[cur][0]);
        uint32_t bs = smem_cast(&Bs[cur][0]);
#pragma unroll
        for (int kc = 0; kc < 2; kc++) {
            uint32_t a[2][4];
#pragma unroll
            for (int mi = 0; mi < 2; mi++) {
                int row = a_row_base + mi * 16;
                int seg = kc * 2 + a_koff;
                uint32_t addr = as + sw_gran(row, seg) * 16;
                LDSM4(a[mi][0], a[mi][1], a[mi][2], a[mi][3], addr);
            }
            uint32_t bf[8][2];
#pragma unroll
            for (int nb = 0; nb < 4; nb++) {
                int row = b_row_base + nb * 16;
                int seg = kc * 2 + b_koff;
                uint32_t addr = bs + sw_gran(row, seg) * 16;
                LDSM4(bf[2 * nb][0], bf[2 * nb][1], bf[2 * nb + 1][0], bf[2 * nb + 1][1], addr);
            }
#pragma unroll
            for (int mi = 0; mi < 2; mi++)
#pragma unroll
                for (int ni = 0; ni < 8; ni++)
                    MMA16816(acc[mi][ni][0], acc[mi][ni][1], acc[mi][ni][2], acc[mi][ni][3],
                             a[mi][0], a[mi][1], a[mi][2], a[mi][3],
                             bf[ni][0], bf[ni][1]);
        }
    }

    // epilogue: fp32 accum -> fp16 C
#pragma unroll
    for (int mi = 0; mi < 2; mi++) {
        int m = m0 + wm * 32 + mi * 16 + (lane >> 2);
#pragma unroll
        for (int ni = 0; ni < 8; ni++) {
            int n = n0 + wn * 64 + ni * 8 + (lane & 3) * 2;
            __half2 lo = __floats2half2_rn(acc[mi][ni][0], acc[mi][ni][1]);
            __half2 hi = __floats2half2_rn(acc[mi][ni][2], acc[mi][ni][3]);
            *reinterpret_cast<__half2*>(C + (size_t)m * N3H + n)       = lo;
            *reinterpret_cast<__half2*>(C + (size_t)(m + 8) * N3H + n) = hi;
        }
    }
}

// ---------------- SRU recurrence, cp.async 8-stage pipeline ----------------
// Grid: 256 blocks = (batch, half-of-H). Block: 128 threads, each owns 2 channels.
// Per step a block consumes 3 x 512B chunks (u0,u1,u2 for its 128 half2 channels).
#define RSTAGES 8

__device__ __forceinline__ float sigf(float x)
{
    return __fdividef(1.f, 1.f + __expf(-x));
}

__global__ void __launch_bounds__(128) sru_rec_kernel(
    const __half* __restrict__ U,    // [L*B][3H] fp16
    const float* __restrict__ v,     // [2H]
    const float* __restrict__ bb,    // [2H]
    __half* __restrict__ hout,       // [L*B][H] fp16 (if store_all)
    float* __restrict__ hlast,       // [B][H] fp32 (if !store_all)
    int store_all)
{
    __shared__ __align__(128) __half2 sU[RSTAGES][3][128];   // 12 KB

    const int tid = threadIdx.x;              // 0..127
    const int b   = blockIdx.x >> 1;          // batch
    const int hh  = blockIdx.x & 1;           // which half of H
    const int hp  = hh * 128 + tid;           // global half2 channel
    const int h   = hp << 1;

    float2 vf = *reinterpret_cast<const float2*>(v + h);
    float2 vr = *reinterpret_cast<const float2*>(v + HID + h);
    float2 bf = *reinterpret_cast<const float2*>(bb + h);
    float2 br = *reinterpret_cast<const float2*>(bb + HID + h);

    // cp.async producer geometry: 96 threads, 16B each (3 chunks x 512B)
    const int chunk = tid >> 5;               // 0..3 (only 0..2 used)
    const int off   = tid & 31;               // 16B granule within chunk
    const char* src_base = (const char*)(U + (size_t)b * N3H + (size_t)chunk * HID + hh * 256) + off * 16;
    const size_t step_bytes = (size_t)BATCH * N3H * 2;

    auto load_stage = [&](int l, int s) {
        if (tid < 96) {
            uint32_t dst = smem_cast(&sU[s][chunk][0]) + off * 16;
            CP_ASYNC16(dst, src_base + (size_t)l * step_bytes);
        }
    };

    // prologue: stages 0..RSTAGES-2
#pragma unroll
    for (int s = 0; s < RSTAGES - 1; s++) {
        load_stage(s, s);
        CP_COMMIT();
    }

    __half2* Hp = reinterpret_cast<__half2*>(hout) + (size_t)b * (HID / 2) + hp;
    const size_t hstep = (size_t)BATCH * (HID / 2);

    float cx = 0.f, cy = 0.f, hx = 0.f, hy = 0.f;

    for (int l = 0; l < L_SEQ; l++) {
        CP_WAIT6();            // stage l resident (RSTAGES-2)
        __syncthreads();       // all consumers past stage (l-1); producers' data visible

        int ln = l + RSTAGES - 1;
        if (ln < L_SEQ) load_stage(ln, ln & (RSTAGES - 1));
        CP_COMMIT();           // unconditional for uniform group count

        int s = l & (RSTAGES - 1);
        float2 u0 = __half22float2(sU[s][0][tid]);
        float2 u1 = __half22float2(sU[s][1][tid]);
        float2 u2 = __half22float2(sU[s][2][tid]);

        float fxa = sigf(fmaf(vf.x, cx, u1.x + bf.x));
        float fya = sigf(fmaf(vf.y, cy, u1.y + bf.y));
        float rxa = sigf(fmaf(vr.x, cx, u2.x + br.x));
        float rya = sigf(fmaf(vr.y, cy, u2.y + br.y));

        cx = fmaf(fxa, cx - u0.x, u0.x);
        cy = fmaf(fya, cy - u0.y, u0.y);
        hx = rxa * cx;
        hy = rya * cy;

        if (store_all) Hp[(size_t)l * hstep] = __floats2half2_rn(hx, hy);
    }

    if (!store_all) {
        hlast[b * HID + h]     = hx;
        hlast[b * HID + h + 1] = hy;
    }
}

// ---------------- final FC: out[b][o] = h2last[b] . fc_w[o] + fc_b[o] ----------------
__global__ void fc_kernel(const float* __restrict__ hl, const float* __restrict__ w,
                          const float* __restrict__ bias, float* __restrict__ out)
{
    int o = blockIdx.x;  // 0..4
    int b = blockIdx.y;  // 0..127
    float p = 0.f;
    for (int h = threadIdx.x; h < HID; h += 128)
        p += hl[b * HID + h] * w[o * HID + h];
#pragma unroll
    for (int s = 16; s > 0; s >>= 1) p += __shfl_down_sync(0xffffffffu, p, s);
    __shared__ float red[4];
    if ((threadIdx.x & 31) == 0) red[threadIdx.x >> 5] = p;
    __syncthreads();
    if (threadIdx.x == 0)
        out[b * OUTD + o] = red[0] + red[1] + red[2] + red[3] + bias[o];
}

// ---------------- launch ----------------
extern "C" void kernel_launch(void* const* d_in, const int* in_sizes, int n_in,
                              void* d_out, int out_size)
{
    const float* x   = (const float*)d_in[0];
    const float* W0  = (const float*)d_in[1];
    const float* v0  = (const float*)d_in[2];
    const float* b0  = (const float*)d_in[3];
    const float* W1  = (const float*)d_in[4];
    const float* v1  = (const float*)d_in[5];
    const float* b1  = (const float*)d_in[6];
    const float* fcw = (const float*)d_in[7];
    const float* fcb = (const float*)d_in[8];
    float* out = (float*)d_out;

    void *p_xh, *p_w0t, *p_w1t, *p_u, *p_h1, *p_h2l;
    cudaGetSymbolAddress(&p_xh,  g_xh);
    cudaGetSymbolAddress(&p_w0t, g_W0t);
    cudaGetSymbolAddress(&p_w1t, g_W1t);
    cudaGetSymbolAddress(&p_u,   g_U);
    cudaGetSymbolAddress(&p_h1,  g_h1);
    cudaGetSymbolAddress(&p_h2l, g_h2last);
    __half* xh  = (__half*)p_xh;
    __half* w0t = (__half*)p_w0t;
    __half* w1t = (__half*)p_w1t;
    __half* U   = (__half*)p_u;
    __half* h1  = (__half*)p_h1;
    float*  h2l = (float*)p_h2l;

    const int nx2 = MROWS * DIM / 2;
    f2h_kernel<<<(nx2 + 255) / 256, 256>>>(x, xh, nx2);
    trans_f2h_kernel<<<dim3(N3H / 32, DIM / 32), dim3(32, 8)>>>(W0, w0t, DIM, N3H);
    trans_f2h_kernel<<<dim3(N3H / 32, HID / 32), dim3(32, 8)>>>(W1, w1t, HID, N3H);

    // layer 0
    gemm_kernel<<<dim3(N3H / 128, MROWS / 128), 256>>>(xh, w0t, U, DIM);
    sru_rec_kernel<<<BATCH * 2, 128>>>(U, v0, b0, h1, h2l, 1);

    // layer 1
    gemm_kernel<<<dim3(N3H / 128, MROWS / 128), 256>>>(h1, w1t, U, HID);
    sru_rec_kernel<<<BATCH * 2, 128>>>(U, v1, b1, h1, h2l, 0);

    // head
    fc_kernel<<<dim3(OUTD, BATCH), 128>>>(h2l, fcw, fcb, out);
}

// round 3
// speedup vs baseline: 1.3510x; 1.0162x over previous
#include <cuda_runtime.h>
#include <cuda_fp16.h>
#include <cstdint>
#include <cstddef>

#define L_SEQ 512
#define BATCH 128
#define DIM   128
#define HID   512
#define OUTD  5
#define N3H   1536
#define MROWS 65536  // L_SEQ*BATCH

// ---------------- scratch (static device globals; no allocations) ----------------
__device__ __align__(256) __half g_xh[MROWS * DIM];          // x in fp16
__device__ __align__(256) __half g_W0t[N3H * DIM];           // W0^T fp16 [n][k]
__device__ __align__(256) __half g_W1t[N3H * HID];           // W1^T fp16 [n][k]
__device__ __align__(256) __half g_U[MROWS * N3H];           // U buffer (reused for both layers)
__device__ __align__(256) __half g_h1[MROWS * HID];          // layer-0 output
__device__ __align__(256) float  g_h2last[BATCH * HID];      // layer-1 last-step output

// ---------------- helpers ----------------
__device__ __forceinline__ uint32_t smem_cast(const void* p)
{
    return (uint32_t)__cvta_generic_to_shared(p);
}

#define CP_ASYNC16(dst, src) asm volatile("cp.async.cg.shared.global [%0], [%1], 16;\n" :: "r"(dst), "l"(src))
#define CP_ASYNC4(dst, src)  asm volatile("cp.async.ca.shared.global [%0], [%1], 4;\n"  :: "r"(dst), "l"(src))
#define CP_COMMIT()          asm volatile("cp.async.commit_group;\n")
#define CP_WAIT1()           asm volatile("cp.async.wait_group 1;\n")
#define CP_WAIT14()          asm volatile("cp.async.wait_group 14;\n")

// ---------------- conversion kernels ----------------
__global__ void f2h_kernel(const float* __restrict__ s, __half* __restrict__ d, int n2)
{
    int i = blockIdx.x * blockDim.x + threadIdx.x;
    if (i < n2) {
        float2 v = reinterpret_cast<const float2*>(s)[i];
        reinterpret_cast<__half2*>(d)[i] = __floats2half2_rn(v.x, v.y);
    }
}

// Tiled transpose + fp32->fp16: Wt[n][k] = (half) W[k][n].
__global__ void trans_f2h_kernel(const float* __restrict__ W, __half* __restrict__ Wt,
                                 int K, int N)
{
    __shared__ float tile[32][33];
    int tx = threadIdx.x;
    int ty = threadIdx.y;
    int nb = blockIdx.x * 32;
    int kb = blockIdx.y * 32;
#pragma unroll
    for (int j = 0; j < 32; j += 8)
        tile[ty + j][tx] = W[(size_t)(kb + ty + j) * N + (nb + tx)];
    __syncthreads();
#pragma unroll
    for (int j = 0; j < 32; j += 8)
        Wt[(size_t)(nb + ty + j) * K + (kb + tx)] = __float2half(tile[tx][ty + j]);
}

__global__ void dummy_kernel() {}   // shifts ncu -s 5 onto the recurrence kernel

// ---------------- GEMM: C[m][n] (fp16, ld=N3H) = A[m][k] * B^T, B given as [n][k] ----------------
#define LDSM4(R0, R1, R2, R3, ADDR) \
    asm volatile("ldmatrix.sync.aligned.m8n8.x4.shared.b16 {%0,%1,%2,%3}, [%4];" \
                 : "=r"(R0), "=r"(R1), "=r"(R2), "=r"(R3) : "r"(ADDR))

#define MMA16816(C0, C1, C2, C3, A0, A1, A2, A3, B0, B1)                              \
    asm volatile("mma.sync.aligned.m16n8k16.row.col.f32.f16.f16.f32 "                  \
                 "{%0,%1,%2,%3}, {%4,%5,%6,%7}, {%8,%9}, {%0,%1,%2,%3};"               \
                 : "+f"(C0), "+f"(C1), "+f"(C2), "+f"(C3)                              \
                 : "r"(A0), "r"(A1), "r"(A2), "r"(A3), "r"(B0), "r"(B1))

__device__ __forceinline__ int sw_gran(int row, int seg)
{
    return ((row >> 1) << 3) | ((((row & 1) << 2) | seg) ^ ((row >> 1) & 7));
}

__global__ void __launch_bounds__(256, 2) gemm_kernel(
    const __half* __restrict__ A,
    const __half* __restrict__ B,
    __half* __restrict__ C,
    int K)
{
    __shared__ __align__(1024) __half As[3][128 * 32];
    __shared__ __align__(1024) __half Bs[3][128 * 32];

    const int tid  = threadIdx.x;
    const int lane = tid & 31;
    const int wid  = tid >> 5;
    const int wm   = wid & 3;
    const int wn   = wid >> 2;
    const int m0   = blockIdx.y * 128;
    const int n0   = blockIdx.x * 128;

    auto load_tile = [&](int buf, int k0) {
        uint32_t as = smem_cast(&As[buf][0]);
        uint32_t bs = smem_cast(&Bs[buf][0]);
#pragma unroll
        for (int i = 0; i < 2; i++) {
            int lin = tid + i * 256;
            int row = lin >> 2;
            int seg = lin & 3;
            int g   = sw_gran(row, seg);
            const __half* ag = A + (size_t)(m0 + row) * K + (k0 + seg * 8);
            const __half* bg = B + (size_t)(n0 + row) * K + (k0 + seg * 8);
            CP_ASYNC16(as + g * 16, ag);
            CP_ASYNC16(bs + g * 16, bg);
        }
    };

    float acc[2][8][4];
#pragma unroll
    for (int mi = 0; mi < 2; mi++)
#pragma unroll
        for (int ni = 0; ni < 8; ni++)
#pragma unroll
            for (int j = 0; j < 4; j++) acc[mi][ni][j] = 0.f;

    const int T = K >> 5;
    load_tile(0, 0);
    CP_COMMIT();
    load_tile(1, 32);
    CP_COMMIT();

    const int a_row_base = wm * 32 + (lane & 15);
    const int a_koff     = lane >> 4;
    const int b_row_base = wn * 64 + (lane & 7) + ((lane & 16) ? 8 : 0);
    const int b_koff     = (lane >> 3) & 1;

    for (int t = 0; t < T; t++) {
        CP_WAIT1();
        __syncthreads();

        if (t + 2 < T) load_tile((t + 2) % 3, (t + 2) << 5);
        CP_COMMIT();

        int cur = t % 3;
        uint32_t as = smem_cast(&As[cur][0]);
        uint32_t bs = smem_cast(&Bs[cur][0]);
#pragma unroll
        for (int kc = 0; kc < 2; kc++) {
            uint32_t a[2][4];
#pragma unroll
            for (int mi = 0; mi < 2; mi++) {
                int row = a_row_base + mi * 16;
                int seg = kc * 2 + a_koff;
                uint32_t addr = as + sw_gran(row, seg) * 16;
                LDSM4(a[mi][0], a[mi][1], a[mi][2], a[mi][3], addr);
            }
            uint32_t bf[8][2];
#pragma unroll
            for (int nb = 0; nb < 4; nb++) {
                int row = b_row_base + nb * 16;
                int seg = kc * 2 + b_koff;
                uint32_t addr = bs + sw_gran(row, seg) * 16;
                LDSM4(bf[2 * nb][0], bf[2 * nb][1], bf[2 * nb + 1][0], bf[2 * nb + 1][1], addr);
            }
#pragma unroll
            for (int mi = 0; mi < 2; mi++)
#pragma unroll
                for (int ni = 0; ni < 8; ni++)
                    MMA16816(acc[mi][ni][0], acc[mi][ni][1], acc[mi][ni][2], acc[mi][ni][3],
                             a[mi][0], a[mi][1], a[mi][2], a[mi][3],
                             bf[ni][0], bf[ni][1]);
        }
    }

#pragma unroll
    for (int mi = 0; mi < 2; mi++) {
        int m = m0 + wm * 32 + mi * 16 + (lane >> 2);
#pragma unroll
        for (int ni = 0; ni < 8; ni++) {
            int n = n0 + wn * 64 + ni * 8 + (lane & 3) * 2;
            __half2 lo = __floats2half2_rn(acc[mi][ni][0], acc[mi][ni][1]);
            __half2 hi = __floats2half2_rn(acc[mi][ni][2], acc[mi][ni][3]);
            *reinterpret_cast<__half2*>(C + (size_t)m * N3H + n)       = lo;
            *reinterpret_cast<__half2*>(C + (size_t)(m + 8) * N3H + n) = hi;
        }
    }
}

// ---------------- SRU recurrence: per-thread cp.async ring, barrier-free ----------------
// Each thread owns ONE half2 channel pair and prefetches its own 3x4B per step into a
// private 16-deep smem ring. No cross-thread sharing -> no __syncthreads in the loop.
#define RSTAGES 16

__device__ __forceinline__ float sigf(float x)
{
    return __fdividef(1.f, 1.f + __expf(-x));
}

__global__ void __launch_bounds__(128) sru_rec_kernel(
    const __half* __restrict__ U,    // [L*B][3H] fp16
    const float* __restrict__ v,     // [2H]
    const float* __restrict__ bb,    // [2H]
    __half* __restrict__ hout,       // [L*B][H] fp16 (if store_all)
    float* __restrict__ hlast,       // [B][H] fp32 (if !store_all)
    int store_all)
{
    __shared__ __align__(128) __half2 sU[RSTAGES][3][128];   // 24 KB

    const int tid = threadIdx.x;                 // 0..127
    const int idx = blockIdx.x * 128 + tid;      // 0..32767
    const int b   = idx >> 8;                    // batch
    const int hp  = idx & 255;                   // half2 channel
    const int h   = hp << 1;

    float2 vf = *reinterpret_cast<const float2*>(v + h);
    float2 vr = *reinterpret_cast<const float2*>(v + HID + h);
    float2 bf = *reinterpret_cast<const float2*>(bb + h);
    float2 br = *reinterpret_cast<const float2*>(bb + HID + h);

    // per-thread source pointers (bytes); chunk c at +c*HID*2, step at +B*N3H*2
    const char* src = (const char*)(U + (size_t)b * N3H + h);
    const size_t step_bytes = (size_t)BATCH * N3H * 2;
    const uint32_t smem0 = smem_cast(&sU[0][0][tid]);   // + ((s*3+c)*128)*4

    auto load_stage = [&](int l, int s) {
        const char* p = src + (size_t)l * step_bytes;
        uint32_t d = smem0 + (uint32_t)(s * 3 * 512);
        CP_ASYNC4(d,        p);
        CP_ASYNC4(d + 512,  p + HID * 2);
        CP_ASYNC4(d + 1024, p + HID * 4);
    };

    // prologue: stages 0..14
#pragma unroll
    for (int s = 0; s < RSTAGES - 1; s++) {
        load_stage(s, s);
        CP_COMMIT();
    }

    __half2* Hp = reinterpret_cast<__half2*>(hout) + (size_t)b * (HID / 2) + hp;
    const size_t hstep = (size_t)BATCH * (HID / 2);

    float cx = 0.f, cy = 0.f, hx = 0.f, hy = 0.f;

    for (int l = 0; l < L_SEQ; l++) {
        CP_WAIT14();                       // stage l resident for THIS thread

        int s = l & (RSTAGES - 1);
        float2 u0 = __half22float2(sU[s][0][tid]);
        float2 u1 = __half22float2(sU[s][1][tid]);
        float2 u2 = __half22float2(sU[s][2][tid]);

        int ln = l + RSTAGES - 1;
        if (ln < L_SEQ) load_stage(ln, ln & (RSTAGES - 1));
        CP_COMMIT();                       // uniform group count

        float fxa = sigf(fmaf(vf.x, cx, u1.x + bf.x));
        float fya = sigf(fmaf(vf.y, cy, u1.y + bf.y));
        float rxa = sigf(fmaf(vr.x, cx, u2.x + br.x));
        float rya = sigf(fmaf(vr.y, cy, u2.y + br.y));

        cx = fmaf(fxa, cx - u0.x, u0.x);
        cy = fmaf(fya, cy - u0.y, u0.y);
        hx = rxa * cx;
        hy = rya * cy;

        if (store_all) Hp[(size_t)l * hstep] = __floats2half2_rn(hx, hy);
    }

    if (!store_all) {
        hlast[b * HID + h]     = hx;
        hlast[b * HID + h + 1] = hy;
    }
}

// ---------------- final FC ----------------
__global__ void fc_kernel(const float* __restrict__ hl, const float* __restrict__ w,
                          const float* __restrict__ bias, float* __restrict__ out)
{
    int o = blockIdx.x;
    int b = blockIdx.y;
    float p = 0.f;
    for (int h = threadIdx.x; h < HID; h += 128)
        p += hl[b * HID + h] * w[o * HID + h];
#pragma unroll
    for (int s = 16; s > 0; s >>= 1) p += __shfl_down_sync(0xffffffffu, p, s);
    __shared__ float red[4];
    if ((threadIdx.x & 31) == 0) red[threadIdx.x >> 5] = p;
    __syncthreads();
    if (threadIdx.x == 0)
        out[b * OUTD + o] = red[0] + red[1] + red[2] + red[3] + bias[o];
}

// ---------------- launch ----------------
extern "C" void kernel_launch(void* const* d_in, const int* in_sizes, int n_in,
                              void* d_out, int out_size)
{
    const float* x   = (const float*)d_in[0];
    const float* W0  = (const float*)d_in[1];
    const float* v0  = (const float*)d_in[2];
    const float* b0  = (const float*)d_in[3];
    const float* W1  = (const float*)d_in[4];
    const float* v1  = (const float*)d_in[5];
    const float* b1  = (const float*)d_in[6];
    const float* fcw = (const float*)d_in[7];
    const float* fcb = (const float*)d_in[8];
    float* out = (float*)d_out;

    void *p_xh, *p_w0t, *p_w1t, *p_u, *p_h1, *p_h2l;
    cudaGetSymbolAddress(&p_xh,  g_xh);
    cudaGetSymbolAddress(&p_w0t, g_W0t);
    cudaGetSymbolAddress(&p_w1t, g_W1t);
    cudaGetSymbolAddress(&p_u,   g_U);
    cudaGetSymbolAddress(&p_h1,  g_h1);
    cudaGetSymbolAddress(&p_h2l, g_h2last);
    __half* xh  = (__half*)p_xh;
    __half* w0t = (__half*)p_w0t;
    __half* w1t = (__half*)p_w1t;
    __half* U   = (__half*)p_u;
    __half* h1  = (__half*)p_h1;
    float*  h2l = (float*)p_h2l;

    const int nx2 = MROWS * DIM / 2;
    f2h_kernel<<<(nx2 + 255) / 256, 256>>>(x, xh, nx2);                      // launch 0
    trans_f2h_kernel<<<dim3(N3H / 32, DIM / 32), dim3(32, 8)>>>(W0, w0t, DIM, N3H);   // 1
    trans_f2h_kernel<<<dim3(N3H / 32, HID / 32), dim3(32, 8)>>>(W1, w1t, HID, N3H);   // 2

    // layer 0
    gemm_kernel<<<dim3(N3H / 128, MROWS / 128), 256>>>(xh, w0t, U, DIM);     // 3
    dummy_kernel<<<1, 1>>>();                                                // 4 (ncu -s 5 -> sru)
    sru_rec_kernel<<<BATCH * 2, 128>>>(U, v0, b0, h1, h2l, 1);               // 5

    // layer 1
    gemm_kernel<<<dim3(N3H / 128, MROWS / 128), 256>>>(h1, w1t, U, HID);     // 6
    sru_rec_kernel<<<BATCH * 2, 128>>>(U, v1, b1, h1, h2l, 0);               // 7

    // head
    fc_kernel<<<dim3(OUTD, BATCH), 128>>>(h2l, fcw, fcb, out);               // 8
}